// round 10
// baseline (speedup 1.0000x reference)
#include <cuda_runtime.h>
#include <cstdint>

#define BATCH_N 2048
#define NCLS    50257
#define KPOS    20
#define THREADS 256
#define JSPLIT  2
#define CHUNK0  25129     // half 0: cols [0, 25129); half 1: [25129, 50257)

#define STAGES      4
#define STAGE_BYTES 12288     // 768 float4
#define STAGE_F4    768

#define LOG2E 1.4426950408889634f
#define LN2   0.6931471805599453f

// smem layout (dynamic):
//   [0, 49152)        : 4 stage buffers of 12288 B
//   [49152, 49184)    : 4 mbarriers (8 B each)
//   [49184, 49216)    : sred[8]
//   [49216, 49296)    : tg[20]
//   [49296, 49304)    : flags (fin, last)
#define SM_MBAR  49152
#define SM_SRED  49184
#define SM_TG    49216
#define SM_FLAGS 49296
#define SMEM_TOTAL 49312

__device__ float        g_part[BATCH_N * JSPLIT];
__device__ float        g_rowloss[BATCH_N];
__device__ unsigned int g_rowcnt[BATCH_N];  // zero-init; finisher resets
__device__ unsigned int g_cnt;              // zero-init; last finisher resets

typedef unsigned long long ull;

__device__ __forceinline__ ull pk2(float lo, float hi) {
    ull r; asm("mov.b64 %0, {%1, %2};" : "=l"(r) : "f"(lo), "f"(hi)); return r;
}
__device__ __forceinline__ void upk2(ull v, float& lo, float& hi) {
    asm("mov.b64 {%0, %1}, %2;" : "=f"(lo), "=f"(hi) : "l"(v));
}
__device__ __forceinline__ ull mul2(ull a, ull b) {
    ull r; asm("mul.rn.f32x2 %0, %1, %2;" : "=l"(r) : "l"(a), "l"(b)); return r;
}
__device__ __forceinline__ ull fma2(ull p, ull e) {   // p *= (1+e)
    ull r; asm("fma.rn.f32x2 %0, %1, %2, %3;" : "=l"(r) : "l"(p), "l"(e), "l"(p)); return r;
}
__device__ __forceinline__ float ex2f(float x) {
    float r; asm("ex2.approx.f32 %0, %1;" : "=f"(r) : "f"(x)); return r;
}
__device__ __forceinline__ float lg2f(float x) {
    float r; asm("lg2.approx.f32 %0, %1;" : "=f"(r) : "f"(x)); return r;
}

// p *= prod_{k}(1 + exp(x_k)) over one float4 (x pre-scaled by log2e via k2)
__device__ __forceinline__ void accf4(float4 v, ull& p, ull k2) {
    ull ta = mul2(pk2(v.x, v.y), k2);
    ull tb = mul2(pk2(v.z, v.w), k2);
    float l0, h0, l1, h1;
    upk2(ta, l0, h0); upk2(tb, l1, h1);
    p = fma2(p, pk2(ex2f(l0), ex2f(h0)));
    p = fma2(p, pk2(ex2f(l1), ex2f(h1)));
}
__device__ __forceinline__ float log_group(ull p) {
    float l, h; upk2(p, l, h);
    return lg2f(l * h);
}
__device__ __forceinline__ float softplus_stable(float x) {
    return fmaxf(x, 0.0f) + __logf(1.0f + __expf(-fabsf(x)));
}

__device__ __forceinline__ void mbar_init(uint32_t a, uint32_t cnt) {
    asm volatile("mbarrier.init.shared.b64 [%0], %1;" :: "r"(a), "r"(cnt) : "memory");
}
__device__ __forceinline__ void mbar_expect_tx(uint32_t a, uint32_t bytes) {
    asm volatile("mbarrier.arrive.expect_tx.shared.b64 _, [%0], %1;" :: "r"(a), "r"(bytes) : "memory");
}
__device__ __forceinline__ void mbar_wait(uint32_t a, uint32_t phase) {
    asm volatile(
        "{\n\t.reg .pred P;\n"
        "W%=:\n\t"
        "mbarrier.try_wait.parity.acquire.cta.shared::cta.b64 P, [%0], %1, 0x989680;\n\t"
        "@P bra D%=;\n\t"
        "bra W%=;\n"
        "D%=:\n\t}"
        :: "r"(a), "r"(phase) : "memory");
}
__device__ __forceinline__ void bulk_g2s(uint32_t dst, const void* src, uint32_t bytes, uint32_t mbar) {
    asm volatile(
        "cp.async.bulk.shared::cta.global.mbarrier::complete_tx::bytes [%0], [%1], %2, [%3];"
        :: "r"(dst), "l"(src), "r"(bytes), "r"(mbar) : "memory");
}

__global__ __launch_bounds__(THREADS, 4)
void mlsm_kernel(const float* __restrict__ in, const int* __restrict__ tgt,
                 float* __restrict__ out) {
    extern __shared__ unsigned char smem_raw[];
    const uint32_t smem_u32 = (uint32_t)__cvta_generic_to_shared(smem_raw);
    float4* __restrict__ buf = (float4*)smem_raw;
    float*  sred  = (float*)(smem_raw + SM_SRED);
    int*    tg    = (int*)  (smem_raw + SM_TG);
    int*    flags = (int*)  (smem_raw + SM_FLAGS);

    const int row  = blockIdx.x >> 1;
    const int half = blockIdx.x & 1;
    const float* __restrict__ rp = in + (size_t)row * NCLS;

    const int c0 = half ? CHUNK0 : 0;
    const int c1 = half ? NCLS   : CHUNK0;
    const float* __restrict__ bp = rp + c0;
    const int n = c1 - c0;

    const int tid = threadIdx.x;
    const ull k2 = pk2(LOG2E, LOG2E);

    // 16B alignment peel (row stride 50257 is odd)
    const int mis  = (int)(((uintptr_t)bp >> 2) & 3);
    const int lead = (4 - mis) & 3;
    const int nvec = (n - lead) >> 2;                 // aligned float4 count
    const int tail = lead + (nvec << 2);
    const uint32_t bulk_bytes = (uint32_t)nvec << 4;
    const int nstages = (nvec + STAGE_F4 - 1) / STAGE_F4;
    const char* __restrict__ gsrc = (const char*)(bp + lead);

    float sp_s  = 0.0f;   // scalar stable softplus (edges)
    float lsum2 = 0.0f;   // sum of lg2(group products)

    for (int i = tid; i < lead; i += THREADS) sp_s += softplus_stable(bp[i]);
    for (int j = tail + tid; j < n; j += THREADS) sp_s += softplus_stable(bp[j]);

    // ── pipeline init + prologue ──
    if (tid == 0) {
        #pragma unroll
        for (int s = 0; s < STAGES; s++) mbar_init(smem_u32 + SM_MBAR + s * 8, 1);
    }
    __syncthreads();
    if (tid == 0) {
        const int pro = nstages < STAGES ? nstages : STAGES;
        for (int s = 0; s < pro; s++) {
            const uint32_t off   = (uint32_t)s * STAGE_BYTES;
            const uint32_t bytes = min((uint32_t)STAGE_BYTES, bulk_bytes - off);
            const uint32_t mb    = smem_u32 + SM_MBAR + s * 8;
            mbar_expect_tx(mb, bytes);
            bulk_g2s(smem_u32 + off, gsrc + off, bytes, mb);
        }
    }

    // ── main pipelined loop ──
    for (int s = 0; s < nstages; s++) {
        const int slot = s & (STAGES - 1);
        const uint32_t ph = (uint32_t)(s >> 2) & 1u;
        mbar_wait(smem_u32 + SM_MBAR + slot * 8, ph);

        const int base = s * STAGE_F4;
        const int fl4  = min(STAGE_F4, nvec - base);
        const float4* __restrict__ sb = buf + slot * STAGE_F4;

        if (fl4 == STAGE_F4) {
            float4 a = sb[tid];
            float4 b = sb[tid + THREADS];
            float4 c = sb[tid + 2 * THREADS];
            ull pA = pk2(1.0f, 1.0f), pB = pk2(1.0f, 1.0f);
            accf4(a, pA, k2); accf4(b, pA, k2);     // group of 8
            accf4(c, pB, k2);                       // group of 4
            lsum2 += log_group(pA) + log_group(pB);
        } else {
            for (int j = tid; j < fl4; j += THREADS) {
                float4 v = sb[j];
                ull p = pk2(1.0f, 1.0f);
                accf4(v, p, k2);
                lsum2 += log_group(p);
            }
        }
        __syncthreads();                            // slot fully consumed

        if (tid == 0 && s + STAGES < nstages) {
            const int s2 = s + STAGES;
            const uint32_t goff  = (uint32_t)s2 * STAGE_BYTES;
            const uint32_t bytes = min((uint32_t)STAGE_BYTES, bulk_bytes - goff);
            const uint32_t mb    = smem_u32 + SM_MBAR + slot * 8;
            mbar_expect_tx(mb, bytes);
            bulk_g2s(smem_u32 + (uint32_t)slot * STAGE_BYTES, gsrc + goff, bytes, mb);
        }
    }

    // ── block reduce: partial of sum softplus over this chunk ──
    float s = sp_s + lsum2 * LN2;
    #pragma unroll
    for (int o = 16; o > 0; o >>= 1) s += __shfl_down_sync(0xFFFFFFFFu, s, o);
    if ((tid & 31) == 0) sred[tid >> 5] = s;
    __syncthreads();
    if (tid == 0) {
        float b = sred[0];
        #pragma unroll
        for (int w = 1; w < THREADS / 32; w++) b += sred[w];
        g_part[blockIdx.x] = b;
        __threadfence();
        unsigned o = atomicAdd(&g_rowcnt[row], 1u);
        flags[0] = (o == JSPLIT - 1) ? 1 : 0;
    }
    __syncthreads();

    // ── per-row finisher: combine halves + target fixup ──
    if (flags[0]) {
        if (tid < 32) {
            if (tid < KPOS) tg[tid] = tgt[row * KPOS + tid];
            __syncwarp();

            float sp = (tid < JSPLIT) ? __ldcg(&g_part[(row << 1) | tid]) : 0.0f;
            sp += __shfl_down_sync(0xFFFFFFFFu, sp, 1);   // lane0: p0 + p1 (fixed order)

            float pos = 0.0f, sub = 0.0f;
            int   uc  = 0;
            if (tid < KPOS) {
                const int t = tg[tid];
                const float x = rp[t];
                const float l = __logf(1.0f + __expf(-fabsf(x)));
                pos = fminf(x, 0.0f) - l;          // log_sigmoid(x)
                bool dup = false;
                #pragma unroll
                for (int j = 0; j < KPOS; j++)
                    if (j < tid && tg[j] == t) dup = true;
                if (!dup) {
                    sub = -fmaxf(x, 0.0f) - l;     // log_sigmoid(-x) at unique label
                    uc  = 1;
                }
            }
            #pragma unroll
            for (int o = 16; o > 0; o >>= 1) {
                pos += __shfl_down_sync(0xFFFFFFFFu, pos, o);
                sub += __shfl_down_sync(0xFFFFFFFFu, sub, o);
                uc  += __shfl_down_sync(0xFFFFFFFFu, uc,  o);
            }
            if (tid == 0) {
                const float s_all    = -sp;
                const float neg_mean = (s_all - sub) / (float)(NCLS - uc);
                g_rowloss[row] = pos * (1.0f / (float)KPOS) + neg_mean;
            }
        }
        if (tid == 0) {
            g_rowcnt[row] = 0;                      // reset for next replay
            __threadfence();
            unsigned o2 = atomicAdd(&g_cnt, 1u);
            flags[1] = (o2 == BATCH_N - 1) ? 1 : 0;
        }
    } else if (tid == 0) {
        flags[1] = 0;
    }
    __syncthreads();

    // ── last finisher: deterministic final mean ──
    if (flags[1]) {
        float t = 0.0f;
        #pragma unroll
        for (int r = 0; r < BATCH_N / THREADS; r++)
            t += __ldcg(&g_rowloss[tid + r * THREADS]);
        #pragma unroll
        for (int o = 16; o > 0; o >>= 1) t += __shfl_down_sync(0xFFFFFFFFu, t, o);
        if ((tid & 31) == 0) sred[tid >> 5] = t;
        __syncthreads();
        if (tid < 32) {
            float b2 = (tid < THREADS / 32) ? sred[tid] : 0.0f;
            #pragma unroll
            for (int o = 16; o > 0; o >>= 1) b2 += __shfl_down_sync(0xFFFFFFFFu, b2, o);
            if (tid == 0) {
                out[0] = -b2 * (1.0f / (float)BATCH_N);
                g_cnt  = 0;                         // reset for next replay
            }
        }
    }
}

extern "C" void kernel_launch(void* const* d_in, const int* in_sizes, int n_in,
                              void* d_out, int out_size) {
    const float* in  = (const float*)d_in[0];
    const int*   tgt = (const int*)d_in[1];
    float*       out = (float*)d_out;
    (void)in_sizes; (void)n_in; (void)out_size;

    cudaFuncSetAttribute(mlsm_kernel, cudaFuncAttributeMaxDynamicSharedMemorySize, SMEM_TOTAL);
    mlsm_kernel<<<BATCH_N * JSPLIT, THREADS, SMEM_TOTAL>>>(in, tgt, out);
}

// round 13
// speedup vs baseline: 1.0369x; 1.0369x over previous
#include <cuda_runtime.h>
#include <cstdint>

#define BATCH_N 2048
#define NCLS    50257
#define KPOS    20
#define THREADS 256
#define JSPLIT  4

#define LOG2E 1.4426950408889634f
#define LN2   0.6931471805599453f

__device__ float        g_part[BATCH_N * JSPLIT];
__device__ float        g_rowloss[BATCH_N];
__device__ unsigned int g_rowcnt[BATCH_N];  // zero-init; finisher resets
__device__ unsigned int g_cnt;              // zero-init; last finisher resets

typedef unsigned long long ull;

__device__ __forceinline__ ull pk2(float lo, float hi) {
    ull r; asm("mov.b64 %0, {%1, %2};" : "=l"(r) : "f"(lo), "f"(hi)); return r;
}
__device__ __forceinline__ void upk2(ull v, float& lo, float& hi) {
    asm("mov.b64 {%0, %1}, %2;" : "=f"(lo), "=f"(hi) : "l"(v));
}
__device__ __forceinline__ ull mul2(ull a, ull b) {
    ull r; asm("mul.rn.f32x2 %0, %1, %2;" : "=l"(r) : "l"(a), "l"(b)); return r;
}
__device__ __forceinline__ ull fma2(ull p, ull e) {   // p *= (1+e)
    ull r; asm("fma.rn.f32x2 %0, %1, %2, %3;" : "=l"(r) : "l"(p), "l"(e), "l"(p)); return r;
}
__device__ __forceinline__ float ex2f(float x) {
    float r; asm("ex2.approx.f32 %0, %1;" : "=f"(r) : "f"(x)); return r;
}
__device__ __forceinline__ float lg2f(float x) {
    float r; asm("lg2.approx.f32 %0, %1;" : "=f"(r) : "f"(x)); return r;
}

// p *= prod_k (1 + exp(x_k)) over one float4 (inputs pre-scaled by log2e)
__device__ __forceinline__ void accf4(float4 v, ull& p, ull k2) {
    ull ta = mul2(pk2(v.x, v.y), k2);
    ull tb = mul2(pk2(v.z, v.w), k2);
    float l0, h0, l1, h1;
    upk2(ta, l0, h0); upk2(tb, l1, h1);
    p = fma2(p, pk2(ex2f(l0), ex2f(h0)));
    p = fma2(p, pk2(ex2f(l1), ex2f(h1)));
}
__device__ __forceinline__ float log_group(ull p) {
    float l, h; upk2(p, l, h);
    return lg2f(l * h);
}
__device__ __forceinline__ float softplus_stable(float x) {
    return fmaxf(x, 0.0f) + __logf(1.0f + __expf(-fabsf(x)));
}

__global__ __launch_bounds__(THREADS, 6)
void mlsm_kernel(const float* __restrict__ in, const int* __restrict__ tgt,
                 float* __restrict__ out) {
    const int row = blockIdx.x >> 2;
    const int q   = blockIdx.x & 3;
    const float* __restrict__ rp = in + (size_t)row * NCLS;

    // quarter bounds: exact integer split of 50257
    const int c0 = (q * NCLS) >> 2;
    const int c1 = ((q + 1) * NCLS) >> 2;
    const float* __restrict__ bp = rp + c0;
    const int n = c1 - c0;

    __shared__ float sred[THREADS / 32];
    __shared__ int   tg[KPOS];
    __shared__ int   fin_sh, last_sh;

    const int tid = threadIdx.x;
    const ull k2 = pk2(LOG2E, LOG2E);

    float sp_s  = 0.0f;   // scalar stable softplus (edges)
    float lsum2 = 0.0f;   // sum of lg2(group products)

    // peel to 16B alignment (row stride 50257 is odd)
    const int mis  = (int)(((uintptr_t)bp >> 2) & 3);
    const int lead = (4 - mis) & 3;
    for (int i = tid; i < lead; i += THREADS) sp_s += softplus_stable(bp[i]);

    const int nvec = (n - lead) >> 2;
    const float4* __restrict__ vp = (const float4*)(bp + lead);

    int i = tid;
    // main loop: 6 float4 in flight (24 elems), one LG2 per 8 elems
    for (; i + 5 * THREADS < nvec; i += 6 * THREADS) {
        float4 v0 = __ldcs(vp + i + 0 * THREADS);
        float4 v1 = __ldcs(vp + i + 1 * THREADS);
        float4 v2 = __ldcs(vp + i + 2 * THREADS);
        float4 v3 = __ldcs(vp + i + 3 * THREADS);
        float4 v4 = __ldcs(vp + i + 4 * THREADS);
        float4 v5 = __ldcs(vp + i + 5 * THREADS);
        ull pA = pk2(1.0f, 1.0f), pB = pk2(1.0f, 1.0f), pC = pk2(1.0f, 1.0f);
        accf4(v0, pA, k2); accf4(v1, pA, k2);
        accf4(v2, pB, k2); accf4(v3, pB, k2);
        accf4(v4, pC, k2); accf4(v5, pC, k2);
        lsum2 += log_group(pA) + log_group(pB) + log_group(pC);
    }
    for (; i < nvec; i += THREADS) {
        float4 v = __ldcs(vp + i);
        ull p = pk2(1.0f, 1.0f);
        accf4(v, p, k2);
        lsum2 += log_group(p);
    }
    for (int j = lead + (nvec << 2) + tid; j < n; j += THREADS) sp_s += softplus_stable(bp[j]);

    // block reduce: partial of sum softplus over this chunk
    float s = sp_s + lsum2 * LN2;
    #pragma unroll
    for (int o = 16; o > 0; o >>= 1) s += __shfl_down_sync(0xFFFFFFFFu, s, o);
    if ((tid & 31) == 0) sred[tid >> 5] = s;
    __syncthreads();
    if (tid == 0) {
        float b = sred[0];
        #pragma unroll
        for (int w = 1; w < THREADS / 32; w++) b += sred[w];
        g_part[blockIdx.x] = b;
        __threadfence();
        unsigned o = atomicAdd(&g_rowcnt[row], 1u);
        fin_sh = (o == JSPLIT - 1) ? 1 : 0;
    }
    __syncthreads();

    // ── per-row finisher: combine quarters + target fixup ──
    if (fin_sh) {
        if (tid < 32) {
            if (tid < KPOS) tg[tid] = tgt[row * KPOS + tid];
            __syncwarp();

            float sp = (tid < JSPLIT) ? __ldcg(&g_part[(row << 2) | tid]) : 0.0f;
            sp += __shfl_down_sync(0xFFFFFFFFu, sp, 2);   // fixed order
            sp += __shfl_down_sync(0xFFFFFFFFu, sp, 1);   // lane0: (p0+p2)+(p1+p3)

            float pos = 0.0f, sub = 0.0f;
            int   uc  = 0;
            if (tid < KPOS) {
                const int t = tg[tid];
                const float x = rp[t];
                const float l = __logf(1.0f + __expf(-fabsf(x)));
                pos = fminf(x, 0.0f) - l;          // log_sigmoid(x)
                bool dup = false;
                #pragma unroll
                for (int j = 0; j < KPOS; j++)
                    if (j < tid && tg[j] == t) dup = true;
                if (!dup) {
                    sub = -fmaxf(x, 0.0f) - l;     // log_sigmoid(-x) at unique label
                    uc  = 1;
                }
            }
            #pragma unroll
            for (int o = 16; o > 0; o >>= 1) {
                pos += __shfl_down_sync(0xFFFFFFFFu, pos, o);
                sub += __shfl_down_sync(0xFFFFFFFFu, sub, o);
                uc  += __shfl_down_sync(0xFFFFFFFFu, uc,  o);
            }
            if (tid == 0) {
                const float s_all    = -sp;
                const float neg_mean = (s_all - sub) / (float)(NCLS - uc);
                g_rowloss[row] = pos * (1.0f / (float)KPOS) + neg_mean;
            }
        }
        if (tid == 0) {
            g_rowcnt[row] = 0;                      // reset for next replay
            __threadfence();
            unsigned o2 = atomicAdd(&g_cnt, 1u);
            last_sh = (o2 == BATCH_N - 1) ? 1 : 0;
        }
    } else if (tid == 0) {
        last_sh = 0;
    }
    __syncthreads();

    // ── last finisher: deterministic final mean ──
    if (last_sh) {
        float t = 0.0f;
        #pragma unroll
        for (int r = 0; r < BATCH_N / THREADS; r++)
            t += __ldcg(&g_rowloss[tid + r * THREADS]);
        #pragma unroll
        for (int o = 16; o > 0; o >>= 1) t += __shfl_down_sync(0xFFFFFFFFu, t, o);
        if ((tid & 31) == 0) sred[tid >> 5] = t;
        __syncthreads();
        if (tid < 32) {
            float b2 = (tid < THREADS / 32) ? sred[tid] : 0.0f;
            #pragma unroll
            for (int o = 16; o > 0; o >>= 1) b2 += __shfl_down_sync(0xFFFFFFFFu, b2, o);
            if (tid == 0) {
                out[0] = -b2 * (1.0f / (float)BATCH_N);
                g_cnt  = 0;                         // reset for next replay
            }
        }
    }
}

extern "C" void kernel_launch(void* const* d_in, const int* in_sizes, int n_in,
                              void* d_out, int out_size) {
    const float* in  = (const float*)d_in[0];
    const int*   tgt = (const int*)d_in[1];
    float*       out = (float*)d_out;
    (void)in_sizes; (void)n_in; (void)out_size;

    mlsm_kernel<<<BATCH_N * JSPLIT, THREADS>>>(in, tgt, out);
}